// round 8
// baseline (speedup 1.0000x reference)
#include <cuda_runtime.h>
#include <cuda_fp16.h>
#include <math.h>
#include <stdint.h>

#define T_TOK 2048
#define HID   1024
#define INTER 512
#define NE    32
#define TOPK  6
#define NGRP  8
#define GSZ   4
#define TKGRP 4
#define NSLOT (T_TOK*TOPK)
#define MAXS  T_TOK
#define SHI   2048

// ---------------- device scratch ----------------
__device__ int   g_cnt[NE];
__device__ int   g_slots[NE*MAXS];
__device__ float g_w[NSLOT];
__device__ __half g_x[T_TOK*HID];
__device__ __half g_upw[NE*INTER*HID];
__device__ __half g_dnw[NE*HID*INTER];
__device__ __half g_shu[SHI*HID];
__device__ __half g_shd[HID*SHI];
__device__ __half g_h[NSLOT*INTER];
__device__ __half g_sh[T_TOK*SHI];
__device__ float g_partial[(size_t)NSLOT*HID];

// ---------------- helpers ----------------
static __device__ __forceinline__ uint32_t s2u(const void* p){
    uint32_t a;
    asm("{ .reg .u64 t; cvta.to.shared.u64 t, %1; cvt.u32.u64 %0, t; }"
        : "=r"(a) : "l"(p));
    return a;
}
static __device__ __forceinline__ void cp16(uint32_t dst, const void* src){
    asm volatile("cp.async.cg.shared.global [%0], [%1], 16;"
                 :: "r"(dst), "l"(src));
}
#define CP_COMMIT() asm volatile("cp.async.commit_group;" ::: "memory")

#define LDSM4(r0,r1,r2,r3,a) \
    asm volatile("ldmatrix.sync.aligned.m8n8.x4.shared.b16 {%0,%1,%2,%3}, [%4];" \
                 : "=r"(r0), "=r"(r1), "=r"(r2), "=r"(r3) : "r"(a))

#define MMA16816(d,a,b) \
    asm volatile("mma.sync.aligned.m16n8k16.row.col.f32.f16.f16.f32 " \
                 "{%0,%1,%2,%3},{%4,%5,%6,%7},{%8,%9},{%0,%1,%2,%3};" \
                 : "+f"((d)[0]), "+f"((d)[1]), "+f"((d)[2]), "+f"((d)[3]) \
                 : "r"((a)[0]), "r"((a)[1]), "r"((a)[2]), "r"((a)[3]), \
                   "r"((b)[0]), "r"((b)[1]))

// ---------------------------------------------------------------------------
// Fused fp32->fp16 converts.
#define X4  (T_TOK*HID/4)
#define U4  (NE*INTER*HID/4)
#define S4  (SHI*HID/4)
#define D4  (NE*HID*INTER/4)
#define SD4 (HID*SHI/4)

static __device__ __forceinline__ void conv4(const float* __restrict__ s,
                                             __half* __restrict__ d, int i){
    float4 v = ((const float4*)s)[i];
    __half2 a = __halves2half2(__float2half_rn(v.x), __float2half_rn(v.y));
    __half2 b = __halves2half2(__float2half_rn(v.z), __float2half_rn(v.w));
    uint2 u; u.x = *(uint32_t*)&a; u.y = *(uint32_t*)&b;
    ((uint2*)d)[i] = u;
}

__global__ __launch_bounds__(256) void conv1_k(
    const float* __restrict__ x, const float* __restrict__ up,
    const float* __restrict__ su)
{
    if (blockIdx.x == 0 && threadIdx.x < NE) g_cnt[threadIdx.x] = 0;
    int i = blockIdx.x * 256 + threadIdx.x;
    if (i < X4)                conv4(x,  g_x,   i);
    else if (i < X4 + U4)      conv4(up, g_upw, i - X4);
    else if (i < X4 + U4 + S4) conv4(su, g_shu, i - X4 - U4);
}

__global__ __launch_bounds__(256) void conv2_k(
    const float* __restrict__ dn, const float* __restrict__ sd)
{
    int i = blockIdx.x * 256 + threadIdx.x;
    if (i < D4)            conv4(dn, g_dnw, i);
    else if (i < D4 + SD4) conv4(sd, g_shd, i - D4);
}

// ---------------------------------------------------------------------------
// Router: one block per token, 128 threads. fp32-exact (validated round 1).
__global__ __launch_bounds__(128) void router_k(
    const float* __restrict__ x,
    const float* __restrict__ gate_w,
    const float* __restrict__ e_bias)
{
    int t = blockIdx.x;
    __shared__ float xs[HID];
    __shared__ float logits[NE];

    const float* xr = x + (size_t)t * HID;
    for (int i = threadIdx.x; i < HID / 4; i += 128)
        ((float4*)xs)[i] = ((const float4*)xr)[i];
    __syncthreads();

    int warp = threadIdx.x >> 5, lane = threadIdx.x & 31;
    for (int e = warp * 8; e < warp * 8 + 8; e++) {
        const float* g = gate_w + (size_t)e * HID;
        float p = 0.f;
        #pragma unroll 8
        for (int h = lane; h < HID; h += 32) p += g[h] * xs[h];
        #pragma unroll
        for (int o = 16; o > 0; o >>= 1) p += __shfl_xor_sync(0xffffffffu, p, o);
        if (lane == 0) logits[e] = p;
    }
    __syncthreads();

    if (threadIdx.x == 0) {
        float scores[NE], sc[NE];
        #pragma unroll
        for (int e = 0; e < NE; e++) {
            scores[e] = 1.f / (1.f + expf(-logits[e]));
            sc[e] = scores[e] + e_bias[e];
        }
        float gs[NGRP];
        #pragma unroll
        for (int g = 0; g < NGRP; g++) {
            float m1 = -1e30f, m2 = -1e30f;
            #pragma unroll
            for (int j = 0; j < GSZ; j++) {
                float v = sc[g * GSZ + j];
                if (v > m1) { m2 = m1; m1 = v; }
                else if (v > m2) { m2 = v; }
            }
            gs[g] = m1 + m2;
        }
        bool gsel[NGRP];
        #pragma unroll
        for (int g = 0; g < NGRP; g++) gsel[g] = false;
        for (int r = 0; r < TKGRP; r++) {
            int best = -1; float bv = -1e30f;
            #pragma unroll
            for (int g = 0; g < NGRP; g++)
                if (!gsel[g] && gs[g] > bv) { bv = gs[g]; best = g; }
            gsel[best] = true;
        }
        float masked[NE];
        #pragma unroll
        for (int e = 0; e < NE; e++) masked[e] = gsel[e >> 2] ? sc[e] : 0.0f;
        bool used[NE];
        #pragma unroll
        for (int e = 0; e < NE; e++) used[e] = false;
        int idx[TOPK]; float wv[TOPK]; float wsum = 0.f;
        for (int r = 0; r < TOPK; r++) {
            int best = -1; float bv = -1e30f;
            #pragma unroll
            for (int e = 0; e < NE; e++)
                if (!used[e] && masked[e] > bv) { bv = masked[e]; best = e; }
            used[best] = true;
            idx[r] = best;
            wv[r] = scores[best];
            wsum += wv[r];
        }
        float inv = 2.5f / (wsum + 1e-20f);
        for (int r = 0; r < TOPK; r++) {
            int e = idx[r];
            int s = t * TOPK + r;
            g_w[s] = wv[r] * inv;
            int pos = atomicAdd(&g_cnt[e], 1);
            g_slots[e * MAXS + pos] = s;
        }
    }
}

// ---------------------------------------------------------------------------
// Merged HMMA grouped GEMM, BK=64, 2-stage cp.async pipeline, packed grid.
// blockIdx.x < NBR*NE: routed (e = x / NBR, nblk = x % NBR);
// else: shared (nblk = x - NBR*NE).
// UP: relu2(+routing-scale routed), fp16 out. !UP: plain, fp32 out.
#define PITCHB 80u
#define TILE32 (128u*PITCHB)       // one 128x32 subtile: 10240 B
#define STGB   (4u*TILE32)         // A0 A1 B0 B1 = 40960 B
#define SMEM_GEMM (2u*STGB)        // 81920 B

// LDFRAGS: aso/bso = subtile base addresses; kb in {0,32} bytes
#define LDFRAGS(buf, aso, bso, kb) do {                                        \
    _Pragma("unroll")                                                          \
    for (int mt_ = 0; mt_ < 4; mt_++) {                                        \
        uint32_t a_ = (aso) + (uint32_t)(wm0 + mt_*16 + aRow) * PITCHB         \
                    + (kb) + aK;                                               \
        LDSM4(av[buf][mt_][0], av[buf][mt_][1],                                \
              av[buf][mt_][2], av[buf][mt_][3], a_);                           \
    }                                                                          \
    _Pragma("unroll")                                                          \
    for (int jp_ = 0; jp_ < 4; jp_ += 2) {                                     \
        uint32_t b_ = (bso)                                                    \
                    + (uint32_t)(wn0 + jp_*8 + bRow) * PITCHB + (kb) + bK;     \
        LDSM4(bv[buf][jp_][0], bv[buf][jp_][1],                                \
              bv[buf][jp_+1][0], bv[buf][jp_+1][1], b_);                       \
    }                                                                          \
} while(0)

#define DOMMA(buf) do {                                                        \
    _Pragma("unroll")                                                          \
    for (int mt_ = 0; mt_ < 4; mt_++)                                          \
        _Pragma("unroll")                                                      \
        for (int jn_ = 0; jn_ < 4; jn_++)                                      \
            MMA16816(acc[mt_][jn_], av[buf][mt_], bv[buf][jn_]);               \
} while(0)

template<bool UP, int NBR>
__global__ __launch_bounds__(256, 2) void moe_gemm(
    const __half* __restrict__ Ar, const __half* __restrict__ Br,
    const __half* __restrict__ As, const __half* __restrict__ Bs,
    float* __restrict__ Cfr, float* __restrict__ Cfs,
    __half* __restrict__ Chr, __half* __restrict__ Chs,
    int NtR, int KR, int NtS, int KS)
{
    const int bx = blockIdx.x;
    const bool sh = (bx >= NBR * NE);
    const int e   = sh ? 0 : (bx / NBR);
    const int nbk = sh ? (bx - NBR * NE) : (bx % NBR);
    const int m_count = sh ? T_TOK : g_cnt[e];
    const int m0 = blockIdx.y * 128;
    if (m0 >= m_count) return;
    const int n0 = nbk * 128;
    const int K  = sh ? KS : KR;
    const int Nt = sh ? NtS : NtR;

    extern __shared__ __align__(128) char smem[];
    const uint32_t sb = s2u(smem);
    const int tid = threadIdx.x, wid = tid >> 5, lane = tid & 31;

    // ---- loader: thread pair (2t,2t+1) loads 2x16B per subtile row ----
    const int lrow = tid >> 1;
    const int lelem = (tid & 1) * 16;
    const int gm = m0 + lrow;
    const int idxr = (gm < m_count) ? gm : 0;
    int arow;
    if (sh) {
        arow = idxr;
    } else {
        int s = g_slots[e * MAXS + idxr];
        arow = UP ? (s / TOPK) : s;
    }
    const __half* pA = (sh ? As : Ar) + (size_t)arow * K + lelem;
    const __half* pB = (sh ? Bs : (Br + (size_t)e * NtR * KR))
                       + (size_t)(n0 + lrow) * K + lelem;
    const uint32_t ldst = (uint32_t)lrow * PITCHB + (uint32_t)(tid & 1) * 32u;

    const int nk = K >> 6;             // chunks of 64

    auto load_stage = [&](int k) {
        const uint32_t so = sb + (uint32_t)(k & 1) * STGB + ldst;
        const int k0 = k << 6;
        #pragma unroll
        for (int c = 0; c < 2; c++) {
            cp16(so + c*TILE32,               pA + k0 + c*32);
            cp16(so + c*TILE32 + 16,          pA + k0 + c*32 + 8);
            cp16(so + (2+c)*TILE32,           pB + k0 + c*32);
            cp16(so + (2+c)*TILE32 + 16,      pB + k0 + c*32 + 8);
        }
        CP_COMMIT();
    };

    load_stage(0); load_stage(1);      // nk >= 8 always

    // ---- compute setup ----
    const int wm0 = (wid & 1) * 64;
    const int wn0 = (wid >> 1) * 32;
    const uint32_t aRow = (uint32_t)(lane & 15);
    const uint32_t aK   = (uint32_t)(lane >> 4) * 16u;
    const uint32_t bRow = (uint32_t)((lane & 7) + ((lane >> 4) & 1) * 8);
    const uint32_t bK   = (uint32_t)((lane >> 3) & 1) * 16u;

    float acc[4][4][4];
    #pragma unroll
    for (int i = 0; i < 4; i++)
        #pragma unroll
        for (int j = 0; j < 4; j++)
            #pragma unroll
            for (int q = 0; q < 4; q++) acc[i][j][q] = 0.f;

    uint32_t av[2][4][4], bv[2][4][2];

    asm volatile("cp.async.wait_group 1;" ::: "memory");  // stage 0 arrived
    __syncthreads();

    for (int k = 0; k < nk; k++) {
        const uint32_t so = sb + (uint32_t)(k & 1) * STGB;
        const uint32_t a0 = so, a1 = so + TILE32;
        const uint32_t b0 = so + 2*TILE32, b1 = so + 3*TILE32;
        // 4 steps of k16; register double-buffer hides LDSM latency
        LDFRAGS(0, a0, b0, 0u);                 // step0 frags (exposed once)
        LDFRAGS(1, a0, b0, 32u); DOMMA(0);      // step0 mma | step1 frags
        LDFRAGS(0, a1, b1, 0u);  DOMMA(1);      // step1 mma | step2 frags
        LDFRAGS(1, a1, b1, 32u); DOMMA(0);      // step2 mma | step3 frags
        DOMMA(1);                               // step3 mma
        __syncthreads();                        // all warps done with stage k
        if (k + 1 < nk) {
            if (k + 2 < nk) {
                load_stage(k + 2);              // overwrite stage k buffer
                asm volatile("cp.async.wait_group 1;" ::: "memory"); // k+1 in
            } else {
                asm volatile("cp.async.wait_group 0;" ::: "memory");
            }
            __syncthreads();                    // stage k+1 visible
        }
    }

    // ---- epilogue ----
    const int rw4 = lane >> 2;
    const int cq  = (lane & 3) * 2;
    #pragma unroll
    for (int mt = 0; mt < 4; mt++) {
        #pragma unroll
        for (int half = 0; half < 2; half++) {
            const int gmi = m0 + wm0 + mt*16 + rw4 + half*8;
            if (gmi >= m_count) continue;
            int crow = gmi; float wsc = 1.f;
            if (!sh) {
                int s = g_slots[e * MAXS + gmi];
                crow = s;
                if (UP) wsc = g_w[s];
            }
            #pragma unroll
            for (int jn = 0; jn < 4; jn++) {
                float v0 = acc[mt][jn][half*2 + 0];
                float v1 = acc[mt][jn][half*2 + 1];
                const int col = n0 + wn0 + jn*8 + cq;
                const size_t off = (size_t)crow * Nt + col;
                if (UP) {
                    v0 = v0 > 0.f ? v0 * v0 : 0.f;
                    v1 = v1 > 0.f ? v1 * v1 : 0.f;
                    v0 *= wsc; v1 *= wsc;
                    __half2 hp = __halves2half2(__float2half_rn(v0),
                                                __float2half_rn(v1));
                    *(uint32_t*)((sh ? Chs : Chr) + off) = *(uint32_t*)&hp;
                } else {
                    *(float2*)((sh ? Cfs : Cfr) + off) = make_float2(v0, v1);
                }
            }
        }
    }
}

// ---------------------------------------------------------------------------
// out[t] += sum_{k<6} g_partial[t*6+k]
__global__ __launch_bounds__(256) void combine_k(float* __restrict__ out) {
    int idx = blockIdx.x * 256 + threadIdx.x;
    int t = idx >> 8;
    int c = idx & 255;
    float4 o = ((float4*)out)[idx];
    #pragma unroll
    for (int k = 0; k < TOPK; k++) {
        const float4 p =
            ((const float4*)g_partial)[(size_t)(t * TOPK + k) * 256 + c];
        o.x += p.x; o.y += p.y; o.z += p.z; o.w += p.w;
    }
    ((float4*)out)[idx] = o;
}

// ---------------------------------------------------------------------------
extern "C" void kernel_launch(void* const* d_in, const int* in_sizes, int n_in,
                              void* d_out, int out_size)
{
    const float* x         = (const float*)d_in[0];
    const float* gate_w    = (const float*)d_in[1];
    const float* e_bias    = (const float*)d_in[2];
    const float* up_w      = (const float*)d_in[3];
    const float* down_w    = (const float*)d_in[4];
    const float* sh_up_w   = (const float*)d_in[5];
    const float* sh_down_w = (const float*)d_in[6];
    float* out = (float*)d_out;

    void *xh, *uw, *dn, *su, *sd, *hb, *shb, *part;
    cudaGetSymbolAddress(&xh,  g_x);
    cudaGetSymbolAddress(&uw,  g_upw);
    cudaGetSymbolAddress(&dn,  g_dnw);
    cudaGetSymbolAddress(&su,  g_shu);
    cudaGetSymbolAddress(&sd,  g_shd);
    cudaGetSymbolAddress(&hb,  g_h);
    cudaGetSymbolAddress(&shb, g_sh);
    cudaGetSymbolAddress(&part, g_partial);

    const int smem = (int)SMEM_GEMM;
    cudaFuncSetAttribute(moe_gemm<true, 4>,
                         cudaFuncAttributeMaxDynamicSharedMemorySize, smem);
    cudaFuncSetAttribute(moe_gemm<false, 8>,
                         cudaFuncAttributeMaxDynamicSharedMemorySize, smem);

    // 0,1: converts  2: router  3: UP GEMM (ncu capture slot)
    conv1_k<<<(X4 + U4 + S4 + 255) / 256, 256>>>(x, up_w, sh_up_w);
    conv2_k<<<(D4 + SD4 + 255) / 256, 256>>>(down_w, sh_down_w);
    router_k<<<T_TOK, 128>>>(x, gate_w, e_bias);

    // UP: routed x in [0,128) = e*4+nblk (INTER/128=4); shared x in [128,144)
    moe_gemm<true, 4><<<dim3(4*NE + SHI/128, T_TOK/128, 1), 256, smem>>>(
        (const __half*)xh, (const __half*)uw,
        (const __half*)xh, (const __half*)su,
        nullptr, nullptr, (__half*)hb, (__half*)shb,
        INTER, HID, SHI, HID);

    // DOWN: routed x in [0,256) = e*8+nblk (HID/128=8); shared x in [256,264)
    moe_gemm<false, 8><<<dim3(8*NE + HID/128, T_TOK/128, 1), 256, smem>>>(
        (const __half*)hb, (const __half*)dn,
        (const __half*)shb, (const __half*)sd,
        (float*)part, out, nullptr, nullptr,
        HID, INTER, HID, SHI);

    combine_k<<<T_TOK, 256>>>(out);
}

// round 9
// speedup vs baseline: 1.0669x; 1.0669x over previous
#include <cuda_runtime.h>
#include <cuda_fp16.h>
#include <math.h>
#include <stdint.h>

#define T_TOK 2048
#define HID   1024
#define INTER 512
#define NE    32
#define TOPK  6
#define NGRP  8
#define GSZ   4
#define TKGRP 4
#define NSLOT (T_TOK*TOPK)
#define MAXS  T_TOK
#define SHI   2048

// ---------------- device scratch ----------------
__device__ int   g_cnt[NE];
__device__ int   g_slots[NE*MAXS];
__device__ float g_w[NSLOT];
__device__ __half g_x[T_TOK*HID];
__device__ __half g_upw[NE*INTER*HID];
__device__ __half g_dnw[NE*HID*INTER];
__device__ __half g_shu[SHI*HID];
__device__ __half g_shd[HID*SHI];
__device__ __half g_h[NSLOT*INTER];
__device__ __half g_sh[T_TOK*SHI];
__device__ float g_partial[(size_t)NSLOT*HID];

// ---------------- helpers ----------------
static __device__ __forceinline__ uint32_t s2u(const void* p){
    uint32_t a;
    asm("{ .reg .u64 t; cvta.to.shared.u64 t, %1; cvt.u32.u64 %0, t; }"
        : "=r"(a) : "l"(p));
    return a;
}
static __device__ __forceinline__ void cp16(uint32_t dst, const void* src){
    asm volatile("cp.async.cg.shared.global [%0], [%1], 16;"
                 :: "r"(dst), "l"(src));
}
#define CP_COMMIT() asm volatile("cp.async.commit_group;" ::: "memory")

#define LDSM4(r0,r1,r2,r3,a) \
    asm volatile("ldmatrix.sync.aligned.m8n8.x4.shared.b16 {%0,%1,%2,%3}, [%4];" \
                 : "=r"(r0), "=r"(r1), "=r"(r2), "=r"(r3) : "r"(a))

#define MMA16816(d,a,b) \
    asm volatile("mma.sync.aligned.m16n8k16.row.col.f32.f16.f16.f32 " \
                 "{%0,%1,%2,%3},{%4,%5,%6,%7},{%8,%9},{%0,%1,%2,%3};" \
                 : "+f"((d)[0]), "+f"((d)[1]), "+f"((d)[2]), "+f"((d)[3]) \
                 : "r"((a)[0]), "r"((a)[1]), "r"((a)[2]), "r"((a)[3]), \
                   "r"((b)[0]), "r"((b)[1]))

// ---------------------------------------------------------------------------
// Fused fp32->fp16 converts.
#define X4  (T_TOK*HID/4)
#define U4  (NE*INTER*HID/4)
#define S4  (SHI*HID/4)
#define D4  (NE*HID*INTER/4)
#define SD4 (HID*SHI/4)

static __device__ __forceinline__ void conv4(const float* __restrict__ s,
                                             __half* __restrict__ d, int i){
    float4 v = ((const float4*)s)[i];
    __half2 a = __halves2half2(__float2half_rn(v.x), __float2half_rn(v.y));
    __half2 b = __halves2half2(__float2half_rn(v.z), __float2half_rn(v.w));
    uint2 u; u.x = *(uint32_t*)&a; u.y = *(uint32_t*)&b;
    ((uint2*)d)[i] = u;
}

__global__ __launch_bounds__(256) void conv1_k(
    const float* __restrict__ x, const float* __restrict__ up,
    const float* __restrict__ su)
{
    if (blockIdx.x == 0 && threadIdx.x < NE) g_cnt[threadIdx.x] = 0;
    int i = blockIdx.x * 256 + threadIdx.x;
    if (i < X4)                conv4(x,  g_x,   i);
    else if (i < X4 + U4)      conv4(up, g_upw, i - X4);
    else if (i < X4 + U4 + S4) conv4(su, g_shu, i - X4 - U4);
}

__global__ __launch_bounds__(256) void conv2_k(
    const float* __restrict__ dn, const float* __restrict__ sd)
{
    int i = blockIdx.x * 256 + threadIdx.x;
    if (i < D4)            conv4(dn, g_dnw, i);
    else if (i < D4 + SD4) conv4(sd, g_shd, i - D4);
}

// ---------------------------------------------------------------------------
// Router: one block per token, 128 threads. fp32-exact (validated round 1).
__global__ __launch_bounds__(128) void router_k(
    const float* __restrict__ x,
    const float* __restrict__ gate_w,
    const float* __restrict__ e_bias)
{
    int t = blockIdx.x;
    __shared__ float xs[HID];
    __shared__ float logits[NE];

    const float* xr = x + (size_t)t * HID;
    for (int i = threadIdx.x; i < HID / 4; i += 128)
        ((float4*)xs)[i] = ((const float4*)xr)[i];
    __syncthreads();

    int warp = threadIdx.x >> 5, lane = threadIdx.x & 31;
    for (int e = warp * 8; e < warp * 8 + 8; e++) {
        const float* g = gate_w + (size_t)e * HID;
        float p = 0.f;
        #pragma unroll 8
        for (int h = lane; h < HID; h += 32) p += g[h] * xs[h];
        #pragma unroll
        for (int o = 16; o > 0; o >>= 1) p += __shfl_xor_sync(0xffffffffu, p, o);
        if (lane == 0) logits[e] = p;
    }
    __syncthreads();

    if (threadIdx.x == 0) {
        float scores[NE], sc[NE];
        #pragma unroll
        for (int e = 0; e < NE; e++) {
            scores[e] = 1.f / (1.f + expf(-logits[e]));
            sc[e] = scores[e] + e_bias[e];
        }
        float gs[NGRP];
        #pragma unroll
        for (int g = 0; g < NGRP; g++) {
            float m1 = -1e30f, m2 = -1e30f;
            #pragma unroll
            for (int j = 0; j < GSZ; j++) {
                float v = sc[g * GSZ + j];
                if (v > m1) { m2 = m1; m1 = v; }
                else if (v > m2) { m2 = v; }
            }
            gs[g] = m1 + m2;
        }
        bool gsel[NGRP];
        #pragma unroll
        for (int g = 0; g < NGRP; g++) gsel[g] = false;
        for (int r = 0; r < TKGRP; r++) {
            int best = -1; float bv = -1e30f;
            #pragma unroll
            for (int g = 0; g < NGRP; g++)
                if (!gsel[g] && gs[g] > bv) { bv = gs[g]; best = g; }
            gsel[best] = true;
        }
        float masked[NE];
        #pragma unroll
        for (int e = 0; e < NE; e++) masked[e] = gsel[e >> 2] ? sc[e] : 0.0f;
        bool used[NE];
        #pragma unroll
        for (int e = 0; e < NE; e++) used[e] = false;
        int idx[TOPK]; float wv[TOPK]; float wsum = 0.f;
        for (int r = 0; r < TOPK; r++) {
            int best = -1; float bv = -1e30f;
            #pragma unroll
            for (int e = 0; e < NE; e++)
                if (!used[e] && masked[e] > bv) { bv = masked[e]; best = e; }
            used[best] = true;
            idx[r] = best;
            wv[r] = scores[best];
            wsum += wv[r];
        }
        float inv = 2.5f / (wsum + 1e-20f);
        for (int r = 0; r < TOPK; r++) {
            int e = idx[r];
            int s = t * TOPK + r;
            g_w[s] = wv[r] * inv;
            int pos = atomicAdd(&g_cnt[e], 1);
            g_slots[e * MAXS + pos] = s;
        }
    }
}

// ---------------------------------------------------------------------------
// Merged HMMA grouped GEMM. BM=128, BN=128, BK=32, 4-stage cp.async pipeline,
// ONE barrier per chunk, register double-buffered fragments.
// Packed grid: blockIdx.x < NBR*NE: routed (e = x/NBR, nblk = x%NBR);
// else shared (nblk = x - NBR*NE).
// UP: relu2(+routing-scale routed), fp16 out. !UP: plain, fp32 out.
#define PITCHB 80u
#define TILEB  (128u*PITCHB)       // 10240 B
#define STGB   (2u*TILEB)          // A,B per stage = 20480 B
#define NSTG   4u
#define SMEM_GEMM (NSTG*STGB)      // 81920 B

#define LDFRAGS(buf, so, kb) do {                                              \
    _Pragma("unroll")                                                          \
    for (int mt_ = 0; mt_ < 4; mt_++) {                                        \
        uint32_t a_ = (so) + (uint32_t)(wm0 + mt_*16 + aRow) * PITCHB          \
                    + (kb) + aK;                                               \
        LDSM4(av[buf][mt_][0], av[buf][mt_][1],                                \
              av[buf][mt_][2], av[buf][mt_][3], a_);                           \
    }                                                                          \
    _Pragma("unroll")                                                          \
    for (int jp_ = 0; jp_ < 4; jp_ += 2) {                                     \
        uint32_t b_ = (so) + TILEB                                             \
                    + (uint32_t)(wn0 + jp_*8 + bRow) * PITCHB + (kb) + bK;     \
        LDSM4(bv[buf][jp_][0], bv[buf][jp_][1],                                \
              bv[buf][jp_+1][0], bv[buf][jp_+1][1], b_);                       \
    }                                                                          \
} while(0)

#define DOMMA(buf) do {                                                        \
    _Pragma("unroll")                                                          \
    for (int mt_ = 0; mt_ < 4; mt_++)                                          \
        _Pragma("unroll")                                                      \
        for (int jn_ = 0; jn_ < 4; jn_++)                                      \
            MMA16816(acc[mt_][jn_], av[buf][mt_], bv[buf][jn_]);               \
} while(0)

template<bool UP, int NBR>
__global__ __launch_bounds__(256, 2) void moe_gemm(
    const __half* __restrict__ Ar, const __half* __restrict__ Br,
    const __half* __restrict__ As, const __half* __restrict__ Bs,
    float* __restrict__ Cfr, float* __restrict__ Cfs,
    __half* __restrict__ Chr, __half* __restrict__ Chs,
    int NtR, int KR, int NtS, int KS)
{
    const int bx = blockIdx.x;
    const bool sh = (bx >= NBR * NE);
    const int e   = sh ? 0 : (bx / NBR);
    const int nbk = sh ? (bx - NBR * NE) : (bx % NBR);
    const int m_count = sh ? T_TOK : g_cnt[e];
    const int m0 = blockIdx.y * 128;
    if (m0 >= m_count) return;
    const int n0 = nbk * 128;
    const int K  = sh ? KS : KR;
    const int Nt = sh ? NtS : NtR;

    extern __shared__ __align__(128) char smem[];
    const uint32_t sb = s2u(smem);
    const int tid = threadIdx.x, wid = tid >> 5, lane = tid & 31;

    // ---- loader: thread pair (2t,2t+1) loads 2x16B of row t ----
    const int lrow = tid >> 1;
    const int lelem = (tid & 1) * 16;
    const int gm = m0 + lrow;
    const int idxr = (gm < m_count) ? gm : 0;
    int arow;
    if (sh) {
        arow = idxr;
    } else {
        int s = g_slots[e * MAXS + idxr];
        arow = UP ? (s / TOPK) : s;
    }
    const __half* pA = (sh ? As : Ar) + (size_t)arow * K + lelem;
    const __half* pB = (sh ? Bs : (Br + (size_t)e * NtR * KR))
                       + (size_t)(n0 + lrow) * K + lelem;
    const uint32_t ldst = (uint32_t)lrow * PITCHB + (uint32_t)(tid & 1) * 32u;

    const int nk = K >> 5;

    auto load_stage = [&](int k) {
        const uint32_t so = sb + (uint32_t)(k & 3) * STGB + ldst;
        const int k0 = k << 5;
        cp16(so,            pA + k0);
        cp16(so + 16,       pA + k0 + 8);
        cp16(so + TILEB,    pB + k0);
        cp16(so + TILEB+16, pB + k0 + 8);
        CP_COMMIT();
    };

    load_stage(0); load_stage(1); load_stage(2);   // nk >= 16 always

    // ---- compute setup ----
    const int wm0 = (wid & 1) * 64;
    const int wn0 = (wid >> 1) * 32;
    const uint32_t aRow = (uint32_t)(lane & 15);
    const uint32_t aK   = (uint32_t)(lane >> 4) * 16u;
    const uint32_t bRow = (uint32_t)((lane & 7) + ((lane >> 4) & 1) * 8);
    const uint32_t bK   = (uint32_t)((lane >> 3) & 1) * 16u;

    float acc[4][4][4];
    #pragma unroll
    for (int i = 0; i < 4; i++)
        #pragma unroll
        for (int j = 0; j < 4; j++)
            #pragma unroll
            for (int q = 0; q < 4; q++) acc[i][j][q] = 0.f;

    uint32_t av[2][4][4], bv[2][4][2];

    // stage 0 arrived + visible; prefetch chunk-0 step-0 frags
    asm volatile("cp.async.wait_group 2;" ::: "memory");
    __syncthreads();
    LDFRAGS(0, sb, 0u);

    for (int k = 0; k < nk; k++) {
        const uint32_t so  = sb + (uint32_t)(k & 3) * STGB;
        const uint32_t son = sb + (uint32_t)((k + 1) & 3) * STGB;
        LDFRAGS(1, so, 32u);            // step1 frags (last read of stage k)
        DOMMA(0);                        // step0 MMAs
        if (k + 3 < nk) load_stage(k + 3);  // writes buf (k-1)%4 (safe: barrier
                                            // at end of iter k-1 gates it)
        DOMMA(1);                        // step1 MMAs
        if (k + 1 < nk) {
            if (k + 3 < nk)      asm volatile("cp.async.wait_group 2;" ::: "memory");
            else if (k + 2 < nk) asm volatile("cp.async.wait_group 1;" ::: "memory");
            else                 asm volatile("cp.async.wait_group 0;" ::: "memory");
            __syncthreads();             // stage k+1 visible; prev reads done
            LDFRAGS(0, son, 0u);         // prefetch next chunk step0
        }
    }

    // ---- epilogue ----
    const int rw4 = lane >> 2;
    const int cq  = (lane & 3) * 2;
    #pragma unroll
    for (int mt = 0; mt < 4; mt++) {
        #pragma unroll
        for (int half = 0; half < 2; half++) {
            const int gmi = m0 + wm0 + mt*16 + rw4 + half*8;
            if (gmi >= m_count) continue;
            int crow = gmi; float wsc = 1.f;
            if (!sh) {
                int s = g_slots[e * MAXS + gmi];
                crow = s;
                if (UP) wsc = g_w[s];
            }
            #pragma unroll
            for (int jn = 0; jn < 4; jn++) {
                float v0 = acc[mt][jn][half*2 + 0];
                float v1 = acc[mt][jn][half*2 + 1];
                const int col = n0 + wn0 + jn*8 + cq;
                const size_t off = (size_t)crow * Nt + col;
                if (UP) {
                    v0 = v0 > 0.f ? v0 * v0 : 0.f;
                    v1 = v1 > 0.f ? v1 * v1 : 0.f;
                    v0 *= wsc; v1 *= wsc;
                    __half2 hp = __halves2half2(__float2half_rn(v0),
                                                __float2half_rn(v1));
                    *(uint32_t*)((sh ? Chs : Chr) + off) = *(uint32_t*)&hp;
                } else {
                    *(float2*)((sh ? Cfs : Cfr) + off) = make_float2(v0, v1);
                }
            }
        }
    }
}

// ---------------------------------------------------------------------------
// out[t] += sum_{k<6} g_partial[t*6+k]
__global__ __launch_bounds__(256) void combine_k(float* __restrict__ out) {
    int idx = blockIdx.x * 256 + threadIdx.x;
    int t = idx >> 8;
    int c = idx & 255;
    float4 o = ((float4*)out)[idx];
    #pragma unroll
    for (int k = 0; k < TOPK; k++) {
        const float4 p =
            ((const float4*)g_partial)[(size_t)(t * TOPK + k) * 256 + c];
        o.x += p.x; o.y += p.y; o.z += p.z; o.w += p.w;
    }
    ((float4*)out)[idx] = o;
}

// ---------------------------------------------------------------------------
extern "C" void kernel_launch(void* const* d_in, const int* in_sizes, int n_in,
                              void* d_out, int out_size)
{
    const float* x         = (const float*)d_in[0];
    const float* gate_w    = (const float*)d_in[1];
    const float* e_bias    = (const float*)d_in[2];
    const float* up_w      = (const float*)d_in[3];
    const float* down_w    = (const float*)d_in[4];
    const float* sh_up_w   = (const float*)d_in[5];
    const float* sh_down_w = (const float*)d_in[6];
    float* out = (float*)d_out;

    void *xh, *uw, *dn, *su, *sd, *hb, *shb, *part;
    cudaGetSymbolAddress(&xh,  g_x);
    cudaGetSymbolAddress(&uw,  g_upw);
    cudaGetSymbolAddress(&dn,  g_dnw);
    cudaGetSymbolAddress(&su,  g_shu);
    cudaGetSymbolAddress(&sd,  g_shd);
    cudaGetSymbolAddress(&hb,  g_h);
    cudaGetSymbolAddress(&shb, g_sh);
    cudaGetSymbolAddress(&part, g_partial);

    const int smem = (int)SMEM_GEMM;
    cudaFuncSetAttribute(moe_gemm<true, 4>,
                         cudaFuncAttributeMaxDynamicSharedMemorySize, smem);
    cudaFuncSetAttribute(moe_gemm<false, 8>,
                         cudaFuncAttributeMaxDynamicSharedMemorySize, smem);

    // 0,1: converts  2: router  3: UP GEMM (ncu capture slot)
    conv1_k<<<(X4 + U4 + S4 + 255) / 256, 256>>>(x, up_w, sh_up_w);
    conv2_k<<<(D4 + SD4 + 255) / 256, 256>>>(down_w, sh_down_w);
    router_k<<<T_TOK, 128>>>(x, gate_w, e_bias);

    // UP: routed x in [0,128) = e*4+nblk; shared x in [128,144)
    moe_gemm<true, 4><<<dim3(4*NE + SHI/128, T_TOK/128, 1), 256, smem>>>(
        (const __half*)xh, (const __half*)uw,
        (const __half*)xh, (const __half*)su,
        nullptr, nullptr, (__half*)hb, (__half*)shb,
        INTER, HID, SHI, HID);

    // DOWN: routed x in [0,256) = e*8+nblk; shared x in [256,264)
    moe_gemm<false, 8><<<dim3(8*NE + HID/128, T_TOK/128, 1), 256, smem>>>(
        (const __half*)hb, (const __half*)dn,
        (const __half*)shb, (const __half*)sd,
        (float*)part, out, nullptr, nullptr,
        HID, INTER, HID, SHI);

    combine_k<<<T_TOK, 256>>>(out);
}